// round 7
// baseline (speedup 1.0000x reference)
#include <cuda_runtime.h>

#define HH  512
#define WW  512
#define CC  32
#define BB  2
#define NLp 50000
#define NRp 20000
#define EPSf 1e-5f
#define FULLMASK 0xffffffffu

// ---------------------------------------------------------------------------
// Folded parameter block per attention branch (matrices transposed [m][o]).
// ---------------------------------------------------------------------------
struct Folded {
    float WqT[CC * CC]; float bq[CC];
    float WkT[CC * CC]; float bkv[CC]; float bki[CC];
    float WvT[CC * CC]; float bvv[CC]; float bvi[CC];
    float pe9v[9 * CC];
    float WoT[CC * CC]; float bo[CC];
};

__device__ Folded g_f1, g_f2;
__device__ int   g_grid_li[BB * HH * WW];
__device__ int   g_grid_ra[BB * HH * WW];
__device__ float g_qp1[BB * (size_t)NLp * CC];
__device__ float g_kk2[BB * (size_t)NLp * CC];
__device__ float g_vv2[BB * (size_t)NLp * CC];
__device__ float g_qp2[BB * (size_t)NRp * CC];
__device__ float g_kk1[BB * (size_t)NRp * CC];
__device__ float g_vv1[BB * (size_t)NRp * CC];
__device__ float g_out1[BB * (size_t)NLp * CC];   // branch1 values, paint-sorted
__device__ float g_out2[BB * (size_t)NRp * CC];   // branch2 values, paint-sorted
__device__ int   g_rl1[BB * NLp];                 // intra-row rank (img_li, dy-gated)
__device__ int   g_rl2[BB * NRp];                 // intra-row rank (img_ra)
__device__ int   g_cnt[4 * HH];                   // per-(img,b,row) painted count
__device__ int   g_base[4 * HH];                  // exclusive scan of g_cnt per (img,b)
__device__ unsigned char g_dym[BB * NLp];
__device__ unsigned int  g_dyflags = 0;           // sticky across replays (same input -> same bits)

__constant__ int SH9[9][2] = {
    {0,0},{-1,0},{1,0},{0,1},{-1,1},{1,1},{0,-1},{-1,-1},{1,-1}
};

struct Params {
    const float *q1w,*q1b,*k1w,*k1b,*v1w,*v1b;
    const float *q2w,*q2b,*k2w,*k2b,*v2w,*v2b;
    const float *posw,*posb;
    const float *a1iw,*a1ib,*a1ow,*a1ob;
    const float *a2iw,*a2ib,*a2ow,*a2ob;
};

__device__ void fold_branch(Folded* f,
                            const float* qw, const float* qb,
                            const float* kw, const float* kb,
                            const float* vw, const float* vb,
                            const float* inw, const float* inb,
                            const float* ow,  const float* ob,
                            const float* posw, const float* posb,
                            int o, int m)
{
    float aq = 0.f, ak = 0.f, av = 0.f;
    #pragma unroll
    for (int i = 0; i < CC; i++) {
        aq += inw[o * CC + i]            * qw[i * CC + m];
        ak += inw[(CC + o) * CC + i]     * kw[i * CC + m];
        av += inw[(2 * CC + o) * CC + i] * vw[i * CC + m];
    }
    f->WqT[m * CC + o] = aq;
    f->WkT[m * CC + o] = ak;
    f->WvT[m * CC + o] = av;
    f->WoT[m * CC + o] = ow[o * CC + m];

    if (m == 0) {
        float bq = inb[o], bk = inb[CC + o], bv = inb[2 * CC + o];
        #pragma unroll
        for (int i = 0; i < CC; i++) {
            bq += inw[o * CC + i]            * qb[i];
            bk += inw[(CC + o) * CC + i]     * kb[i];
            bv += inw[(2 * CC + o) * CC + i] * vb[i];
        }
        f->bq[o]  = bq;
        f->bkv[o] = bk;  f->bki[o] = inb[CC + o];
        f->bvv[o] = bv;  f->bvi[o] = inb[2 * CC + o];
        f->bo[o]  = ob[o];
    }
    if (m < 9) {
        float s0 = (float)SH9[m][0], s1 = (float)SH9[m][1];
        float acc = 0.f;
        #pragma unroll
        for (int i = 0; i < CC; i++) {
            float pe = s0 * posw[i * 2] + s1 * posw[i * 2 + 1] + posb[i];
            acc += inw[(2 * CC + o) * CC + i] * pe;
        }
        f->pe9v[m * CC + o] = acc;
    }
}

// ---------------------------------------------------------------------------
// Fused setup: prep (block 0) + dy probe (1..10) + clear (11..2058)
//            + build grids (2059..2605).
// ---------------------------------------------------------------------------
#define SETUP_BLOCKS 2606

__global__ void __launch_bounds__(256) setup_kernel(Params P,
    const int* __restrict__ li_c, const int* __restrict__ ra_c,
    const unsigned int* __restrict__ dyw)
{
    int bid = blockIdx.x, tid = threadIdx.x;
    if (bid == 0) {
        for (int pair = tid; pair < 1024; pair += 256) {
            int o = pair >> 5, m = pair & 31;
            fold_branch(&g_f1, P.q1w, P.q1b, P.k1w, P.k1b, P.v1w, P.v1b,
                        P.a1iw, P.a1ib, P.a1ow, P.a1ob, P.posw, P.posb, o, m);
            fold_branch(&g_f2, P.q2w, P.q2b, P.k2w, P.k2b, P.v2w, P.v2b,
                        P.a2iw, P.a2ib, P.a2ow, P.a2ob, P.posw, P.posb, o, m);
        }
    } else if (bid <= 10) {
        unsigned int f = 0;
        for (int i = (bid - 1) * 256 + tid; i < (BB * NRp) / 4; i += 2560) {
            unsigned int w = dyw[i];
            unsigned int b0 = w & 0xffu, b1 = (w >> 8) & 0xffu,
                         b2 = (w >> 16) & 0xffu, b3 = (w >> 24) & 0xffu;
            if (b0 >= 2u || b1 >= 2u || b2 >= 2u || b3 >= 2u) f |= 1u;
            if ((w & 0xffffff00u) != 0u) f |= 2u;
        }
        if (f) atomicOr(&g_dyflags, f);
    } else if (bid <= 2058) {
        int i = (bid - 11) * 256 + tid;
        if (i < BB * HH * WW) { g_grid_li[i] = -1; g_grid_ra[i] = -1; }
        if (i < BB * NLp) g_dym[i] = 0;
    } else {
        int i = (bid - 2059) * 256 + tid;
        if (i < BB * NLp) {
            int b = i / NLp;
            g_grid_li[b * HH * WW + li_c[i * 2] * WW + li_c[i * 2 + 1]] = i - b * NLp;
        } else if (i < BB * (NLp + NRp)) {
            int j = i - BB * NLp;
            int b = j / NRp;
            g_grid_ra[b * HH * WW + ra_c[j * 2] * WW + ra_c[j * 2 + 1]] = j - b * NRp;
        }
    }
}

// ---------------------------------------------------------------------------
// Dynamic-lidar mask (5x5 window, mod-(H+1,W+1) wraparound quirk preserved).
// ---------------------------------------------------------------------------
__global__ void dy_kernel(const int* __restrict__ ra_coors,
                          const void* __restrict__ dy)
{
    int t = blockIdx.x * blockDim.x + threadIdx.x;
    if (t >= BB * NRp * 25) return;
    int s = t % 25;
    int r = t / 25;

    unsigned int flags = g_dyflags;
    bool is_dy;
    if (flags & 1u)      is_dy = ((const unsigned int*)dy)[r] != 0u;
    else if (flags & 2u) is_dy = ((const unsigned char*)dy)[r] != 0;
    else                 is_dy = ((const unsigned int*)dy)[r] != 0u;
    if (!is_dy) return;

    int b  = r / NRp;
    int nx = ra_coors[r * 2]     + (s / 5) - 2;
    int ny = ra_coors[r * 2 + 1] + (s % 5) - 2;
    nx = nx < 0 ? nx + (HH + 1) : (nx >= (HH + 1) ? nx - (HH + 1) : nx);
    ny = ny < 0 ? ny + (WW + 1) : (ny >= (WW + 1) ? ny - (WW + 1) : ny);
    if (nx >= HH || ny >= WW) return;
    int idx = g_grid_li[b * HH * WW + nx * WW + ny];
    if (idx >= 0) g_dym[b * NLp + idx] = 1;
}

// ---------------------------------------------------------------------------
// rankA: per (img, b, row): intra-row paint rank for each painted pillar
// (ballot+popc prefix over 512 cells) + per-row painted count.
// ---------------------------------------------------------------------------
__global__ void __launch_bounds__(256) rankA_kernel()
{
    __shared__ unsigned int masks[16];
    __shared__ int wpfx[16];

    int bid = blockIdx.x;
    int x   = bid & (HH - 1);
    int b   = (bid >> 9) & 1;
    int img = bid >> 10;
    int tid = threadIdx.x;

    const int* grid = img ? g_grid_ra : g_grid_li;
    int* rl = img ? g_rl2 : g_rl1;
    const int N = img ? NRp : NLp;

    int idxk[2]; int flagk[2];
    #pragma unroll
    for (int k = 0; k < 2; k++) {
        int y = tid + k * 256;
        int idx = grid[b * HH * WW + x * WW + y];
        int flag = idx >= 0 && (img || g_dym[b * NLp + (idx < 0 ? 0 : idx)]);
        idxk[k] = idx; flagk[k] = flag;
        unsigned int m = __ballot_sync(FULLMASK, flag);
        if ((tid & 31) == 0) masks[k * 8 + (tid >> 5)] = m;
    }
    __syncthreads();
    if (tid < 16) {
        int s = 0;
        for (int w = 0; w < tid; w++) s += __popc(masks[w]);
        wpfx[tid] = s;
        if (tid == 15) g_cnt[bid] = s + __popc(masks[15]);
    }
    __syncthreads();
    #pragma unroll
    for (int k = 0; k < 2; k++) {
        if (flagk[k]) {
            int y = tid + k * 256;
            int w = y >> 5, bit = y & 31;
            int pref = wpfx[w] + __popc(masks[w] & ((1u << bit) - 1u));
            rl[b * N + idxk[k]] = pref;
        }
    }
}

// rankB: exclusive scan of the 512 row counts for each of 4 (img,b) segments.
__global__ void rankB_kernel()
{
    int tid = threadIdx.x;
    int w = tid >> 5, lane = tid & 31;
    if (w >= 4) return;
    int carry = 0;
    for (int ch = 0; ch < 16; ch++) {
        int v = g_cnt[w * 512 + ch * 32 + lane];
        int s = v;
        #pragma unroll
        for (int off = 1; off < 32; off <<= 1) {
            int t = __shfl_up_sync(FULLMASK, s, off);
            if (lane >= off) s += t;
        }
        g_base[w * 512 + ch * 32 + lane] = carry + s - v;
        carry += __shfl_sync(FULLMASK, s, 31);
    }
}

// ---------------------------------------------------------------------------
// Projection: weights register-resident per warp; x broadcast via smem
// (1 STS + 8 LDS.128 instead of 32 SHFL). Grid-stride per modality range.
// ---------------------------------------------------------------------------
__global__ void __launch_bounds__(128) proj_kernel(
    const float* __restrict__ li_f, const float* __restrict__ ra_f,
    const float* __restrict__ ln_li_w, const float* __restrict__ ln_li_b,
    const float* __restrict__ ln_ra_w, const float* __restrict__ ln_ra_b)
{
    __shared__ float xs[4 * 32];

    int lane = threadIdx.x & 31;
    int wid  = threadIdx.x >> 5;
    int gw   = (blockIdx.x * blockDim.x + threadIdx.x) >> 5;
    int nw   = (gridDim.x * blockDim.x) >> 5;
    int WL   = (nw * 5) / 7;

    bool lidar = gw < WL;
    const Folded* fq  = lidar ? &g_f1 : &g_f2;
    const Folded* fkv = lidar ? &g_f2 : &g_f1;
    const float* feats = lidar ? li_f : ra_f;
    const float* lnw = lidar ? ln_li_w : ln_ra_w;
    const float* lnb = lidar ? ln_li_b : ln_ra_b;
    float* qp = lidar ? g_qp1 : g_qp2;
    float* kk = lidar ? g_kk2 : g_kk1;
    float* vv = lidar ? g_vv2 : g_vv1;
    const int NP  = lidar ? BB * NLp : BB * NRp;
    int start  = lidar ? gw : gw - WL;
    int stride = lidar ? WL : nw - WL;

    float wq[CC], wk[CC], wv[CC];
    #pragma unroll
    for (int m = 0; m < CC; m++) {
        wq[m] = fq->WqT[m * CC + lane];
        wk[m] = fkv->WkT[m * CC + lane];
        wv[m] = fkv->WvT[m * CC + lane];
    }
    float bq = fq->bq[lane], bk = fkv->bkv[lane], bv = fkv->bvv[lane];
    float lw = lnw[lane],    lb = lnb[lane];
    float* xw = xs + wid * 32;

    for (int p = start; p < NP; p += stride) {
        float v = feats[(size_t)p * CC + lane];
        float s = v;
        #pragma unroll
        for (int off = 16; off; off >>= 1) s += __shfl_xor_sync(FULLMASK, s, off);
        float mu = s * (1.f / 32.f);
        float d  = v - mu;
        float ss = d * d;
        #pragma unroll
        for (int off = 16; off; off >>= 1) ss += __shfl_xor_sync(FULLMASK, ss, off);
        float xn = d * rsqrtf(ss * (1.f / 32.f) + EPSf) * lw + lb;

        __syncwarp();
        xw[lane] = xn;
        __syncwarp();

        float aq = bq, ak = bk, av = bv;
        #pragma unroll
        for (int i = 0; i < 8; i++) {
            float4 xv = *(const float4*)(xw + i * 4);
            aq = fmaf(wq[4*i+0], xv.x, aq); aq = fmaf(wq[4*i+1], xv.y, aq);
            aq = fmaf(wq[4*i+2], xv.z, aq); aq = fmaf(wq[4*i+3], xv.w, aq);
            ak = fmaf(wk[4*i+0], xv.x, ak); ak = fmaf(wk[4*i+1], xv.y, ak);
            ak = fmaf(wk[4*i+2], xv.z, ak); ak = fmaf(wk[4*i+3], xv.w, ak);
            av = fmaf(wv[4*i+0], xv.x, av); av = fmaf(wv[4*i+1], xv.y, av);
            av = fmaf(wv[4*i+2], xv.z, av); av = fmaf(wv[4*i+3], xv.w, av);
        }
        size_t o = (size_t)p * CC + lane;
        qp[o] = aq; kk[o] = ak; vv[o] = av;
    }
}

// ---------------------------------------------------------------------------
// Attention: warp per query pillar; out-proj broadcast via smem LDS.128;
// writes compact output ALREADY IN PAINT ORDER via rank arrays.
// ---------------------------------------------------------------------------
__global__ void __launch_bounds__(128) attn_kernel(
    const int* __restrict__ li_c, const int* __restrict__ ra_c)
{
    __shared__ float os[4 * 32];

    int lane = threadIdx.x & 31;
    int wid  = threadIdx.x >> 5;
    int gw   = (blockIdx.x * blockDim.x + threadIdx.x) >> 5;
    int nw   = (gridDim.x * blockDim.x) >> 5;
    int WL   = (nw * 5) / 7;

    bool b1 = gw < WL;
    const Folded* f   = b1 ? &g_f1 : &g_f2;
    const int*  coors = b1 ? li_c : ra_c;
    const int*  grid  = b1 ? g_grid_ra : g_grid_li;
    const float* qp   = b1 ? g_qp1 : g_qp2;
    const float* kk   = b1 ? g_kk1 : g_kk2;
    const float* vv   = b1 ? g_vv1 : g_vv2;
    const int*  rl    = b1 ? g_rl1 : g_rl2;
    const int*  rowb  = g_base + (b1 ? 0 : 1024);
    float* outc       = b1 ? g_out1 : g_out2;
    const int N = b1 ? NLp : NRp;
    const int M = b1 ? NRp : NLp;
    int start  = b1 ? gw : gw - WL;
    int stride = b1 ? WL : nw - WL;

    float wo[CC];
    #pragma unroll
    for (int l = 0; l < CC; l++) wo[l] = f->WoT[l * CC + lane];
    float pe[9];
    #pragma unroll
    for (int j = 0; j < 9; j++) pe[j] = f->pe9v[j * CC + lane];
    float bki = f->bki[lane], bvi = f->bvi[lane], bo = f->bo[lane];
    float* ow = os + wid * 32;

    for (int p = start; p < BB * N; p += stride) {
        if (b1 && !g_dym[p]) continue;

        int b  = p >= N;
        int2 c = ((const int2*)coors)[p];
        float q = qp[(size_t)p * CC + lane];
        const int*   gb  = grid + b * HH * WW;
        const float* kkb = kk + (size_t)b * M * CC;
        const float* vvb = vv + (size_t)b * M * CC;

        float sj[9], vpj[9];
        #pragma unroll
        for (int j = 0; j < 9; j++) {
            int nx = c.x + SH9[j][0], ny = c.y + SH9[j][1];
            int idx = -1;
            if ((unsigned)nx < HH && (unsigned)ny < WW) idx = gb[nx * WW + ny];
            float kp, vp;
            if (idx >= 0) {
                kp = kkb[(size_t)idx * CC + lane];
                vp = vvb[(size_t)idx * CC + lane] + pe[j];
            } else {
                kp = bki;
                vp = bvi;
            }
            float pr = q * kp;
            pr += __shfl_xor_sync(FULLMASK, pr, 8);
            pr += __shfl_xor_sync(FULLMASK, pr, 4);
            pr += __shfl_xor_sync(FULLMASK, pr, 2);
            pr += __shfl_xor_sync(FULLMASK, pr, 1);
            sj[j]  = pr * 0.25f;
            vpj[j] = vp;
        }

        float mx = sj[0];
        #pragma unroll
        for (int j = 1; j < 9; j++) mx = fmaxf(mx, sj[j]);
        float den = 0.f, o = 0.f;
        #pragma unroll
        for (int j = 0; j < 9; j++) {
            float e = expf(sj[j] - mx);
            den += e;
            o = fmaf(e, vpj[j], o);
        }
        o /= den;

        __syncwarp();
        ow[lane] = o;
        __syncwarp();

        float acc = bo;
        #pragma unroll
        for (int i = 0; i < 8; i++) {
            float4 ov = *(const float4*)(ow + i * 4);
            acc = fmaf(wo[4*i+0], ov.x, acc); acc = fmaf(wo[4*i+1], ov.y, acc);
            acc = fmaf(wo[4*i+2], ov.z, acc); acc = fmaf(wo[4*i+3], ov.w, acc);
        }

        int dst = b * N + rowb[b * 512 + c.x] + rl[p];
        outc[(size_t)dst * CC + lane] = acc;
    }
}

// ---------------------------------------------------------------------------
// Paint: sequential reads of paint-ordered values; coalesced float4 stores.
// Prefix recomputed per row from the grid (matches rankA exactly).
// ---------------------------------------------------------------------------
__global__ void __launch_bounds__(256) paint_kernel(float* __restrict__ out)
{
    __shared__ unsigned int masks[16];
    __shared__ int wpfx[16];

    int bid = blockIdx.x;
    int x   = bid & (HH - 1);
    int b   = (bid >> 9) & 1;
    int img = bid >> 10;
    int tid = threadIdx.x;

    const int* grid = img ? g_grid_ra : g_grid_li;
    const float* vals = img ? g_out2 : g_out1;
    const int N = img ? NRp : NLp;

    #pragma unroll
    for (int k = 0; k < 2; k++) {
        int y = tid + k * 256;
        int idx = grid[b * HH * WW + x * WW + y];
        int flag = idx >= 0 && (img || g_dym[b * NLp + (idx < 0 ? 0 : idx)]);
        unsigned int m = __ballot_sync(FULLMASK, flag);
        if ((tid & 31) == 0) masks[k * 8 + (tid >> 5)] = m;
    }
    __syncthreads();
    if (tid < 16) {
        int s = 0;
        for (int w = 0; w < tid; w++) s += __popc(masks[w]);
        wpfx[tid] = s;
    }
    __syncthreads();

    int y4 = (tid & 127) * 4;
    int cofs = tid >> 7;
    int base = b * N + g_base[img * 1024 + b * 512 + x];

    int pidx[4]; int fl[4];
    #pragma unroll
    for (int i = 0; i < 4; i++) {
        int y = y4 + i;
        int w = y >> 5, bit = y & 31;
        fl[i]   = (masks[w] >> bit) & 1u;
        pidx[i] = base + wpfx[w] + __popc(masks[w] & ((1u << bit) - 1u));
    }

    size_t obase = ((size_t)img * BB + b) * CC * (HH * WW) + (size_t)x * WW;

    #pragma unroll
    for (int c0 = 0; c0 < CC; c0 += 2) {
        int c = c0 + cofs;
        float4 o;
        o.x = fl[0] ? vals[(size_t)pidx[0] * CC + c] : 0.f;
        o.y = fl[1] ? vals[(size_t)pidx[1] * CC + c] : 0.f;
        o.z = fl[2] ? vals[(size_t)pidx[2] * CC + c] : 0.f;
        o.w = fl[3] ? vals[(size_t)pidx[3] * CC + c] : 0.f;
        *(float4*)(out + obase + (size_t)c * (HH * WW) + y4) = o;
    }
}

// ---------------------------------------------------------------------------
// Host launcher
// ---------------------------------------------------------------------------
extern "C" void kernel_launch(void* const* d_in, const int* in_sizes, int n_in,
                              void* d_out, int out_size)
{
    const float* li_f = (const float*)d_in[0];
    const int*   li_c = (const int*)d_in[1];
    const float* ra_f = (const float*)d_in[2];
    const int*   ra_c = (const int*)d_in[3];
    const void*  dy   = d_in[4];
    const float* ln_li_w = (const float*)d_in[5];
    const float* ln_li_b = (const float*)d_in[6];
    const float* ln_ra_w = (const float*)d_in[7];
    const float* ln_ra_b = (const float*)d_in[8];

    Params P;
    P.q1w = (const float*)d_in[9];   P.q1b = (const float*)d_in[10];
    P.k1w = (const float*)d_in[11];  P.k1b = (const float*)d_in[12];
    P.v1w = (const float*)d_in[13];  P.v1b = (const float*)d_in[14];
    P.q2w = (const float*)d_in[15];  P.q2b = (const float*)d_in[16];
    P.k2w = (const float*)d_in[17];  P.k2b = (const float*)d_in[18];
    P.v2w = (const float*)d_in[19];  P.v2b = (const float*)d_in[20];
    P.posw = (const float*)d_in[21]; P.posb = (const float*)d_in[22];
    P.a1iw = (const float*)d_in[23]; P.a1ib = (const float*)d_in[24];
    P.a1ow = (const float*)d_in[25]; P.a1ob = (const float*)d_in[26];
    P.a2iw = (const float*)d_in[27]; P.a2ib = (const float*)d_in[28];
    P.a2ow = (const float*)d_in[29]; P.a2ob = (const float*)d_in[30];

    setup_kernel<<<SETUP_BLOCKS, 256>>>(P, li_c, ra_c, (const unsigned int*)dy);
    dy_kernel<<<(BB * NRp * 25 + 255) / 256, 256>>>(ra_c, dy);
    rankA_kernel<<<2 * BB * HH, 256>>>();
    proj_kernel<<<1480, 128>>>(li_f, ra_f, ln_li_w, ln_li_b, ln_ra_w, ln_ra_b);  // profiled slot
    rankB_kernel<<<1, 128>>>();
    attn_kernel<<<1480, 128>>>(li_c, ra_c);
    paint_kernel<<<2 * BB * HH, 256>>>((float*)d_out);
}

// round 8
// speedup vs baseline: 1.0918x; 1.0918x over previous
#include <cuda_runtime.h>

#define HH  512
#define WW  512
#define CC  32
#define BB  2
#define NLp 50000
#define NRp 20000
#define EPSf 1e-5f
#define FULLMASK 0xffffffffu

// ---------------------------------------------------------------------------
// Folded parameter block per attention branch (matrices transposed [m][o]).
// ---------------------------------------------------------------------------
struct Folded {
    float WqT[CC * CC]; float bq[CC];
    float WkT[CC * CC]; float bkv[CC]; float bki[CC];
    float WvT[CC * CC]; float bvv[CC]; float bvi[CC];
    float pe9v[9 * CC];
    float WoT[CC * CC]; float bo[CC];
};

__device__ Folded g_f1, g_f2;
__device__ int   g_grid_li[BB * HH * WW];
__device__ int   g_grid_ra[BB * HH * WW];
__device__ float g_qp1[BB * (size_t)NLp * CC];
__device__ float g_kk2[BB * (size_t)NLp * CC];
__device__ float g_vv2[BB * (size_t)NLp * CC];
__device__ float g_qp2[BB * (size_t)NRp * CC];
__device__ float g_kk1[BB * (size_t)NRp * CC];
__device__ float g_vv1[BB * (size_t)NRp * CC];
__device__ float g_out1[BB * (size_t)NLp * CC];
__device__ float g_out2[BB * (size_t)NRp * CC];
__device__ unsigned char g_dym[BB * NLp];
__device__ unsigned int  g_dyflags = 0;   // sticky across replays (same input -> same bits)

__constant__ int SH9[9][2] = {
    {0,0},{-1,0},{1,0},{0,1},{-1,1},{1,1},{0,-1},{-1,-1},{1,-1}
};

struct Params {
    const float *q1w,*q1b,*k1w,*k1b,*v1w,*v1b;
    const float *q2w,*q2b,*k2w,*k2b,*v2w,*v2b;
    const float *posw,*posb;
    const float *a1iw,*a1ib,*a1ow,*a1ob;
    const float *a2iw,*a2ib,*a2ow,*a2ob;
};

__device__ void fold_branch(Folded* f,
                            const float* qw, const float* qb,
                            const float* kw, const float* kb,
                            const float* vw, const float* vb,
                            const float* inw, const float* inb,
                            const float* ow,  const float* ob,
                            const float* posw, const float* posb,
                            int o, int m)
{
    float aq = 0.f, ak = 0.f, av = 0.f;
    #pragma unroll
    for (int i = 0; i < CC; i++) {
        aq += inw[o * CC + i]            * qw[i * CC + m];
        ak += inw[(CC + o) * CC + i]     * kw[i * CC + m];
        av += inw[(2 * CC + o) * CC + i] * vw[i * CC + m];
    }
    f->WqT[m * CC + o] = aq;
    f->WkT[m * CC + o] = ak;
    f->WvT[m * CC + o] = av;
    f->WoT[m * CC + o] = ow[o * CC + m];

    if (m == 0) {
        float bq = inb[o], bk = inb[CC + o], bv = inb[2 * CC + o];
        #pragma unroll
        for (int i = 0; i < CC; i++) {
            bq += inw[o * CC + i]            * qb[i];
            bk += inw[(CC + o) * CC + i]     * kb[i];
            bv += inw[(2 * CC + o) * CC + i] * vb[i];
        }
        f->bq[o]  = bq;
        f->bkv[o] = bk;  f->bki[o] = inb[CC + o];
        f->bvv[o] = bv;  f->bvi[o] = inb[2 * CC + o];
        f->bo[o]  = ob[o];
    }
    if (m < 9) {
        float s0 = (float)SH9[m][0], s1 = (float)SH9[m][1];
        float acc = 0.f;
        #pragma unroll
        for (int i = 0; i < CC; i++) {
            float pe = s0 * posw[i * 2] + s1 * posw[i * 2 + 1] + posb[i];
            acc += inw[(2 * CC + o) * CC + i] * pe;
        }
        f->pe9v[m * CC + o] = acc;
    }
}

// ---------------------------------------------------------------------------
// Fused setup: prep (block 0) + dy probe (1..10) + clear (11..2058)
//            + build grids (2059..2605).
// ---------------------------------------------------------------------------
#define SETUP_BLOCKS 2606

__global__ void __launch_bounds__(256) setup_kernel(Params P,
    const int* __restrict__ li_c, const int* __restrict__ ra_c,
    const unsigned int* __restrict__ dyw)
{
    int bid = blockIdx.x, tid = threadIdx.x;
    if (bid == 0) {
        for (int pair = tid; pair < 1024; pair += 256) {
            int o = pair >> 5, m = pair & 31;
            fold_branch(&g_f1, P.q1w, P.q1b, P.k1w, P.k1b, P.v1w, P.v1b,
                        P.a1iw, P.a1ib, P.a1ow, P.a1ob, P.posw, P.posb, o, m);
            fold_branch(&g_f2, P.q2w, P.q2b, P.k2w, P.k2b, P.v2w, P.v2b,
                        P.a2iw, P.a2ib, P.a2ow, P.a2ob, P.posw, P.posb, o, m);
        }
    } else if (bid <= 10) {
        unsigned int f = 0;
        for (int i = (bid - 1) * 256 + tid; i < (BB * NRp) / 4; i += 2560) {
            unsigned int w = dyw[i];
            unsigned int b0 = w & 0xffu, b1 = (w >> 8) & 0xffu,
                         b2 = (w >> 16) & 0xffu, b3 = (w >> 24) & 0xffu;
            if (b0 >= 2u || b1 >= 2u || b2 >= 2u || b3 >= 2u) f |= 1u;
            if ((w & 0xffffff00u) != 0u) f |= 2u;
        }
        if (f) atomicOr(&g_dyflags, f);
    } else if (bid <= 2058) {
        int i = (bid - 11) * 256 + tid;
        if (i < BB * HH * WW) { g_grid_li[i] = -1; g_grid_ra[i] = -1; }
        if (i < BB * NLp) g_dym[i] = 0;
    } else {
        int i = (bid - 2059) * 256 + tid;
        if (i < BB * NLp) {
            int b = i / NLp;
            g_grid_li[b * HH * WW + li_c[i * 2] * WW + li_c[i * 2 + 1]] = i - b * NLp;
        } else if (i < BB * (NLp + NRp)) {
            int j = i - BB * NLp;
            int b = j / NRp;
            g_grid_ra[b * HH * WW + ra_c[j * 2] * WW + ra_c[j * 2 + 1]] = j - b * NRp;
        }
    }
}

// ---------------------------------------------------------------------------
// Dynamic-lidar mask (5x5 window, mod-(H+1,W+1) wraparound quirk preserved).
// ---------------------------------------------------------------------------
__global__ void dy_kernel(const int* __restrict__ ra_coors,
                          const void* __restrict__ dy)
{
    int t = blockIdx.x * blockDim.x + threadIdx.x;
    if (t >= BB * NRp * 25) return;
    int s = t % 25;
    int r = t / 25;

    unsigned int flags = g_dyflags;
    bool is_dy;
    if (flags & 1u)      is_dy = ((const unsigned int*)dy)[r] != 0u;
    else if (flags & 2u) is_dy = ((const unsigned char*)dy)[r] != 0;
    else                 is_dy = ((const unsigned int*)dy)[r] != 0u;
    if (!is_dy) return;

    int b  = r / NRp;
    int nx = ra_coors[r * 2]     + (s / 5) - 2;
    int ny = ra_coors[r * 2 + 1] + (s % 5) - 2;
    nx = nx < 0 ? nx + (HH + 1) : (nx >= (HH + 1) ? nx - (HH + 1) : nx);
    ny = ny < 0 ? ny + (WW + 1) : (ny >= (WW + 1) ? ny - (WW + 1) : ny);
    if (nx >= HH || ny >= WW) return;
    int idx = g_grid_li[b * HH * WW + nx * WW + ny];
    if (idx >= 0) g_dym[b * NLp + idx] = 1;
}

// ---------------------------------------------------------------------------
// Projection v2: thread-per-pillar, smem staging, zero shuffles, high ILP.
// Block handles 256 pillars of one modality. Weights in smem (broadcast LDS).
// ---------------------------------------------------------------------------
#define PPB 256
#define NBL_LI ((BB * NLp + PPB - 1) / PPB)   // 391
#define NBL_RA ((BB * NRp + PPB - 1) / PPB)   // 157

__device__ __forceinline__ void matvec32(const float* __restrict__ w,
                                         const float* __restrict__ bias,
                                         const float* __restrict__ xrow,
                                         float* __restrict__ dst)
{
    float acc[32];
    #pragma unroll
    for (int o = 0; o < 32; o++) acc[o] = bias[o];
    #pragma unroll 1
    for (int m = 0; m < 32; m++) {
        float xm = xrow[m];
        const float4* wrow = (const float4*)(w + m * 32);
        #pragma unroll
        for (int o4 = 0; o4 < 8; o4++) {
            float4 wv = wrow[o4];
            acc[o4 * 4 + 0] = fmaf(wv.x, xm, acc[o4 * 4 + 0]);
            acc[o4 * 4 + 1] = fmaf(wv.y, xm, acc[o4 * 4 + 1]);
            acc[o4 * 4 + 2] = fmaf(wv.z, xm, acc[o4 * 4 + 2]);
            acc[o4 * 4 + 3] = fmaf(wv.w, xm, acc[o4 * 4 + 3]);
        }
    }
    float4* d4 = (float4*)dst;
    #pragma unroll
    for (int o4 = 0; o4 < 8; o4++) {
        float4 v;
        v.x = acc[o4 * 4 + 0]; v.y = acc[o4 * 4 + 1];
        v.z = acc[o4 * 4 + 2]; v.w = acc[o4 * 4 + 3];
        d4[o4] = v;
    }
}

__global__ void __launch_bounds__(256) proj2_kernel(
    const float* __restrict__ li_f, const float* __restrict__ ra_f,
    const float* __restrict__ ln_li_w, const float* __restrict__ ln_li_b,
    const float* __restrict__ ln_ra_w, const float* __restrict__ ln_ra_b)
{
    __shared__ float xs[PPB * 33];                       // 33.8 KB, pad 33
    __shared__ float wq[1024], wk[1024], wv[1024];       // 12 KB
    __shared__ float bqs[32], bks[32], bvs[32], lnws[32], lnbs[32];

    int tid = threadIdx.x;
    bool lidar = blockIdx.x < NBL_LI;
    const Folded* fq  = lidar ? &g_f1 : &g_f2;
    const Folded* fkv = lidar ? &g_f2 : &g_f1;
    const float* feats = lidar ? li_f : ra_f;
    const float* lnw = lidar ? ln_li_w : ln_ra_w;
    const float* lnb = lidar ? ln_li_b : ln_ra_b;
    float* qp = lidar ? g_qp1 : g_qp2;
    float* kk = lidar ? g_kk2 : g_kk1;
    float* vv = lidar ? g_vv2 : g_vv1;
    const int NP = lidar ? BB * NLp : BB * NRp;
    int p0 = (lidar ? blockIdx.x : blockIdx.x - NBL_LI) * PPB;
    int count = min(PPB, NP - p0);

    // weights + biases + LN params into smem
    for (int i = tid; i < 1024; i += 256) {
        wq[i] = fq->WqT[i];
        wk[i] = fkv->WkT[i];
        wv[i] = fkv->WvT[i];
    }
    if (tid < 32) {
        bqs[tid]  = fq->bq[tid];
        bks[tid]  = fkv->bkv[tid];
        bvs[tid]  = fkv->bvv[tid];
        lnws[tid] = lnw[tid];
        lnbs[tid] = lnb[tid];
    }

    // stage features: coalesced float4 global -> padded smem rows
    const float4* src = (const float4*)(feats + (size_t)p0 * CC);
    for (int i = tid; i < count * 8; i += 256) {
        float4 v = src[i];
        float* d = xs + (i >> 3) * 33 + (i & 7) * 4;
        d[0] = v.x; d[1] = v.y; d[2] = v.z; d[3] = v.w;
    }
    __syncthreads();

    if (tid < count) {
        float* xrow = xs + tid * 33;

        // LayerNorm in registers (no shuffles)
        float x[32];
        #pragma unroll
        for (int i = 0; i < 32; i++) x[i] = xrow[i];
        float s0 = 0.f, s1 = 0.f, s2 = 0.f, s3 = 0.f;
        #pragma unroll
        for (int i = 0; i < 8; i++) {
            s0 += x[4 * i + 0]; s1 += x[4 * i + 1];
            s2 += x[4 * i + 2]; s3 += x[4 * i + 3];
        }
        float mu = ((s0 + s1) + (s2 + s3)) * (1.f / 32.f);
        float v0 = 0.f, v1 = 0.f, v2 = 0.f, v3 = 0.f;
        #pragma unroll
        for (int i = 0; i < 8; i++) {
            float d0 = x[4 * i + 0] - mu, d1 = x[4 * i + 1] - mu;
            float d2 = x[4 * i + 2] - mu, d3 = x[4 * i + 3] - mu;
            v0 = fmaf(d0, d0, v0); v1 = fmaf(d1, d1, v1);
            v2 = fmaf(d2, d2, v2); v3 = fmaf(d3, d3, v3);
        }
        float rs = rsqrtf(((v0 + v1) + (v2 + v3)) * (1.f / 32.f) + EPSf);
        #pragma unroll
        for (int i = 0; i < 32; i++)
            xrow[i] = (x[i] - mu) * rs * lnws[i] + lnbs[i];

        // three folded matvecs, direct vector stores
        size_t off = (size_t)(p0 + tid) * CC;
        matvec32(wq, bqs, xrow, qp + off);
        matvec32(wk, bks, xrow, kk + off);
        matvec32(wv, bvs, xrow, vv + off);
    }
}

// ---------------------------------------------------------------------------
// Attention (R4 layout): warp per query pillar, weights register-resident,
// grid-stride over pillars; compact [N,C] output.
// ---------------------------------------------------------------------------
template<int B1>
__global__ void __launch_bounds__(256)
attn_kernel(const int* __restrict__ coors)
{
    const Folded* f   = B1 ? &g_f1 : &g_f2;
    const int*   grid = B1 ? g_grid_ra : g_grid_li;
    const float* qp   = B1 ? g_qp1 : g_qp2;
    const float* kk   = B1 ? g_kk1 : g_kk2;
    const float* vv   = B1 ? g_vv1 : g_vv2;
    float* outc       = B1 ? g_out1 : g_out2;
    const int N = B1 ? NLp : NRp;
    const int M = B1 ? NRp : NLp;

    int lane = threadIdx.x & 31;
    int gw   = (blockIdx.x * blockDim.x + threadIdx.x) >> 5;
    int nw   = (gridDim.x * blockDim.x) >> 5;

    float wo[CC];
    #pragma unroll
    for (int l = 0; l < CC; l++) wo[l] = f->WoT[l * CC + lane];
    float pe[9];
    #pragma unroll
    for (int j = 0; j < 9; j++) pe[j] = f->pe9v[j * CC + lane];
    float bki = f->bki[lane], bvi = f->bvi[lane], bo = f->bo[lane];

    for (int p = gw; p < BB * N; p += nw) {
        if (B1 && !g_dym[p]) continue;

        int b  = p >= N;                       // BB == 2
        int2 c = ((const int2*)coors)[p];
        float q = qp[(size_t)p * CC + lane];
        const int*   gb  = grid + b * HH * WW;
        const float* kkb = kk + (size_t)b * M * CC;
        const float* vvb = vv + (size_t)b * M * CC;

        float sj[9], vpj[9];
        #pragma unroll
        for (int j = 0; j < 9; j++) {
            int nx = c.x + SH9[j][0], ny = c.y + SH9[j][1];
            int idx = -1;
            if ((unsigned)nx < HH && (unsigned)ny < WW) idx = gb[nx * WW + ny];
            float kp, vp;
            if (idx >= 0) {
                kp = kkb[(size_t)idx * CC + lane];
                vp = vvb[(size_t)idx * CC + lane] + pe[j];
            } else {
                kp = bki;
                vp = bvi;
            }
            float pr = q * kp;
            pr += __shfl_xor_sync(FULLMASK, pr, 8);
            pr += __shfl_xor_sync(FULLMASK, pr, 4);
            pr += __shfl_xor_sync(FULLMASK, pr, 2);
            pr += __shfl_xor_sync(FULLMASK, pr, 1);
            sj[j]  = pr * 0.25f;
            vpj[j] = vp;
        }

        float mx = sj[0];
        #pragma unroll
        for (int j = 1; j < 9; j++) mx = fmaxf(mx, sj[j]);
        float den = 0.f, o = 0.f;
        #pragma unroll
        for (int j = 0; j < 9; j++) {
            float e = expf(sj[j] - mx);
            den += e;
            o = fmaf(e, vpj[j], o);
        }
        o /= den;

        float acc = bo;
        #pragma unroll
        for (int l = 0; l < CC; l++) {
            float ol = __shfl_sync(FULLMASK, o, l);
            acc = fmaf(wo[l], ol, acc);
        }
        outc[(size_t)p * CC + lane] = acc;
    }
}

// ---------------------------------------------------------------------------
// Paint (R4 layout): full dense output with coalesced float4 stores.
// ---------------------------------------------------------------------------
__global__ void __launch_bounds__(256) paint_kernel(float* __restrict__ out)
{
    __shared__ int idxrow[WW];

    int bid = blockIdx.x;
    int x   = bid & (HH - 1);
    int b   = (bid >> 9) & (BB - 1);
    int img = bid >> 10;
    int tid = threadIdx.x;

    const int* grid = img ? g_grid_ra : g_grid_li;
    const float* vals = img ? g_out2 : g_out1;
    int N = img ? NRp : NLp;

    #pragma unroll
    for (int k = 0; k < 2; k++) {
        int y = tid + k * 256;
        int idx = grid[b * HH * WW + x * WW + y];
        if (!img && idx >= 0 && !g_dym[b * NLp + idx]) idx = -1;
        idxrow[y] = idx;
    }
    __syncthreads();

    int y4 = (tid & 127) * 4;
    int cofs = tid >> 7;
    int i0 = idxrow[y4], i1 = idxrow[y4 + 1], i2 = idxrow[y4 + 2], i3 = idxrow[y4 + 3];

    size_t base = ((size_t)img * BB + b) * CC * (HH * WW) + (size_t)x * WW;
    const float* vb = vals + (size_t)b * N * CC;

    #pragma unroll
    for (int c0 = 0; c0 < CC; c0 += 2) {
        int c = c0 + cofs;
        float4 o;
        o.x = i0 >= 0 ? vb[(size_t)i0 * CC + c] : 0.f;
        o.y = i1 >= 0 ? vb[(size_t)i1 * CC + c] : 0.f;
        o.z = i2 >= 0 ? vb[(size_t)i2 * CC + c] : 0.f;
        o.w = i3 >= 0 ? vb[(size_t)i3 * CC + c] : 0.f;
        *(float4*)(out + base + (size_t)c * (HH * WW) + y4) = o;
    }
}

// ---------------------------------------------------------------------------
// Host launcher
// ---------------------------------------------------------------------------
extern "C" void kernel_launch(void* const* d_in, const int* in_sizes, int n_in,
                              void* d_out, int out_size)
{
    const float* li_f = (const float*)d_in[0];
    const int*   li_c = (const int*)d_in[1];
    const float* ra_f = (const float*)d_in[2];
    const int*   ra_c = (const int*)d_in[3];
    const void*  dy   = d_in[4];
    const float* ln_li_w = (const float*)d_in[5];
    const float* ln_li_b = (const float*)d_in[6];
    const float* ln_ra_w = (const float*)d_in[7];
    const float* ln_ra_b = (const float*)d_in[8];

    Params P;
    P.q1w = (const float*)d_in[9];   P.q1b = (const float*)d_in[10];
    P.k1w = (const float*)d_in[11];  P.k1b = (const float*)d_in[12];
    P.v1w = (const float*)d_in[13];  P.v1b = (const float*)d_in[14];
    P.q2w = (const float*)d_in[15];  P.q2b = (const float*)d_in[16];
    P.k2w = (const float*)d_in[17];  P.k2b = (const float*)d_in[18];
    P.v2w = (const float*)d_in[19];  P.v2b = (const float*)d_in[20];
    P.posw = (const float*)d_in[21]; P.posb = (const float*)d_in[22];
    P.a1iw = (const float*)d_in[23]; P.a1ib = (const float*)d_in[24];
    P.a1ow = (const float*)d_in[25]; P.a1ob = (const float*)d_in[26];
    P.a2iw = (const float*)d_in[27]; P.a2ib = (const float*)d_in[28];
    P.a2ow = (const float*)d_in[29]; P.a2ob = (const float*)d_in[30];

    setup_kernel<<<SETUP_BLOCKS, 256>>>(P, li_c, ra_c, (const unsigned int*)dy);
    dy_kernel<<<(BB * NRp * 25 + 255) / 256, 256>>>(ra_c, dy);
    proj2_kernel<<<NBL_LI + NBL_RA, 256>>>(li_f, ra_f, ln_li_w, ln_li_b,
                                           ln_ra_w, ln_ra_b);
    attn_kernel<1><<<592, 256>>>(li_c);
    attn_kernel<0><<<592, 256>>>(ra_c);
    paint_kernel<<<2 * BB * HH, 256>>>((float*)d_out);
}